// round 15
// baseline (speedup 1.0000x reference)
#include <cuda_runtime.h>
#include <cuda_fp16.h>
#include <math.h>
#include <stdint.h>

// ---------------------------------------------------------------------------
// Problem constants
// ---------------------------------------------------------------------------
#define BATCH 16
#define CH 3
#define IMG 512
#define PATCH 16
#define NTOK 1024
#define MTOT (BATCH * NTOK)    // 16384
#define DMODEL 768
#define FDIM 3072
#define QKVDIM 2304
#define NHEAD 12
#define DHEAD 64
#define WINSZ 64
#define NWIN 16

typedef __half f16;

// ---------------------------------------------------------------------------
// Static device scratch: single fp16 plane activations/weights,
// fp32 for LN input, qkv, residuals, output.
// ---------------------------------------------------------------------------
__device__ f16 g_A0[(size_t)MTOT * DMODEL];    // im2col
__device__ f16 g_wT[(size_t)DMODEL * DMODEL];  // patch weight T [k][d]
__device__ f16 g_qkvW[(size_t)DMODEL * QKVDIM];
__device__ f16 g_projW[(size_t)DMODEL * DMODEL];
__device__ f16 g_ff1W[(size_t)DMODEL * FDIM];
__device__ f16 g_ff2W[(size_t)FDIM * DMODEL];

__device__ float g_y[(size_t)MTOT * DMODEL];
__device__ float g_x0[(size_t)MTOT * DMODEL];
__device__ f16   g_x0h[(size_t)MTOT * DMODEL];
__device__ f16   g_hh[(size_t)MTOT * FDIM];
__device__ f16   g_yh[(size_t)MTOT * DMODEL];
__device__ float g_qkv[(size_t)MTOT * QKVDIM];
__device__ f16   g_attnh[(size_t)MTOT * DMODEL];
__device__ float g_x2[(size_t)MTOT * DMODEL];
__device__ f16   g_x2h[(size_t)MTOT * DMODEL];

// ---------------------------------------------------------------------------
// Helpers
// ---------------------------------------------------------------------------
__device__ __forceinline__ float gelu_tanh(float x) {
    float x3 = x * x * x;
    return 0.5f * x * (1.0f + tanhf(0.7978845608028654f * (x + 0.044715f * x3)));
}
__device__ __forceinline__ uint32_t smem_u32(const void* p) {
    return (uint32_t)__cvta_generic_to_shared(p);
}
__device__ __forceinline__ void cpa16(uint32_t dst, const void* src) {
    asm volatile("cp.async.cg.shared.global [%0], [%1], 16;" :: "r"(dst), "l"(src) : "memory");
}
__device__ __forceinline__ void cpa_commit() {
    asm volatile("cp.async.commit_group;" ::: "memory");
}
template <int N>
__device__ __forceinline__ void cpa_wait() {
    asm volatile("cp.async.wait_group %0;" :: "n"(N) : "memory");
}
__device__ __forceinline__ void ldsmx4(uint32_t& r0, uint32_t& r1, uint32_t& r2, uint32_t& r3, uint32_t a) {
    asm volatile("ldmatrix.sync.aligned.m8n8.x4.shared.b16 {%0,%1,%2,%3},[%4];"
                 : "=r"(r0), "=r"(r1), "=r"(r2), "=r"(r3) : "r"(a));
}
__device__ __forceinline__ void ldsmx4t(uint32_t& r0, uint32_t& r1, uint32_t& r2, uint32_t& r3, uint32_t a) {
    asm volatile("ldmatrix.sync.aligned.m8n8.x4.trans.shared.b16 {%0,%1,%2,%3},[%4];"
                 : "=r"(r0), "=r"(r1), "=r"(r2), "=r"(r3) : "r"(a));
}
__device__ __forceinline__ void mma_f16(float* d, const uint32_t* a, const uint32_t* b) {
    asm volatile("mma.sync.aligned.m16n8k16.row.col.f32.f16.f16.f32 "
                 "{%0,%1,%2,%3},{%4,%5,%6,%7},{%8,%9},{%0,%1,%2,%3};"
                 : "+f"(d[0]), "+f"(d[1]), "+f"(d[2]), "+f"(d[3])
                 : "r"(a[0]), "r"(a[1]), "r"(a[2]), "r"(a[3]), "r"(b[0]), "r"(b[1]));
}

// ---------------------------------------------------------------------------
// Producers
// ---------------------------------------------------------------------------
__global__ void im2col_kernel(const float* __restrict__ in) {
    size_t idx = (size_t)blockIdx.x * blockDim.x + threadIdx.x;
    size_t total = (size_t)MTOT * DMODEL;
    if (idx >= total) return;
    int k = (int)(idx % DMODEL);
    int m = (int)(idx / DMODEL);
    int q = k & 15;
    int p = (k >> 4) & 15;
    int c = k >> 8;
    int wp = m & 31;
    int hp = (m >> 5) & 31;
    int b = m >> 10;
    size_t src = (((size_t)(b * CH + c) * IMG) + (hp * PATCH + p)) * IMG + (wp * PATCH + q);
    g_A0[idx] = __float2half_rn(in[src]);
}

// patch_w [d][k] -> wT[k][d]
__global__ void pack_wT_kernel(const float* __restrict__ pw) {
    int idx = blockIdx.x * blockDim.x + threadIdx.x;
    if (idx >= DMODEL * DMODEL) return;
    int d = idx % DMODEL;
    int k = idx / DMODEL;
    g_wT[idx] = __float2half_rn(pw[(size_t)d * DMODEL + k]);
}

__global__ void convert_kernel(const float* __restrict__ src, f16* __restrict__ dst, int n) {
    int idx = blockIdx.x * blockDim.x + threadIdx.x;
    if (idx >= n) return;
    dst[idx] = __float2half_rn(src[idx]);
}

// ---------------------------------------------------------------------------
// Tensor-core GEMM: block 128x256, BK=32, 8 warps (warp tile 64x64), fp16,
// 1 MMA per product, 4:1 MMA:LDSM ratio, 3-stage cp.async ring,
// anti-phased warp halves. 1 CTA/SM.
// ---------------------------------------------------------------------------
#define AST 40    // As row stride (f16): 32 + 8 pad
#define BST 264   // Bs row stride: 256 + 8 pad
#define A_BYTES (128 * AST * 2)    // 10240
#define B_BYTES (32 * BST * 2)     // 16896
#define STAGE_BYTES (A_BYTES + B_BYTES)   // 27136
#define NSTAGE 3
#define GEMM_SMEM (NSTAGE * STAGE_BYTES)  // 81408

template <bool GELU, bool RES, bool WF32, bool WH>
__global__ __launch_bounds__(256, 1) void mma_gemm(
    const f16* __restrict__ A, const f16* __restrict__ B,
    const float* __restrict__ bias, const float* __restrict__ res,
    float* __restrict__ Cf, f16* __restrict__ Ch,
    int M, int N, int K)
{
    extern __shared__ char dsm[];
    const uint32_t base = smem_u32(dsm);
    auto offA = [&](int st) { return (uint32_t)(st * STAGE_BYTES); };
    auto offB = [&](int st) { return (uint32_t)(st * STAGE_BYTES + A_BYTES); };

    const int tid = threadIdx.x;
    const int l = tid & 31;
    const int w = tid >> 5;
    const int wm = (w & 1) * 64;     // 2 warps in M
    const int wn = (w >> 1) * 64;    // 4 warps in N
    const int phase = (w >> 2) & 1;  // anti-phase selector
    const int m0 = blockIdx.y * 128;
    const int n0 = blockIdx.x * 256;

    float acc[4][8][4];
#pragma unroll
    for (int i = 0; i < 4; i++)
#pragma unroll
        for (int j = 0; j < 8; j++)
#pragma unroll
            for (int r = 0; r < 4; r++) acc[i][j][r] = 0.f;

    auto load_tile = [&](int st, int k0) {
        // A: 128x32 f16 = 512 16B-lanes
#pragma unroll
        for (int s = 0; s < 2; s++) {
            int c = tid + s * 256;
            int row = c >> 2, cc = (c & 3) * 8;
            size_t g = (size_t)(m0 + row) * K + k0 + cc;
            uint32_t d = (uint32_t)(row * AST + cc) * 2;
            cpa16(base + offA(st) + d, A + g);
        }
        // B: 32x256 f16 = 1024 lanes
#pragma unroll
        for (int s = 0; s < 4; s++) {
            int c = tid + s * 256;
            int row = c >> 5, cc = (c & 31) * 8;
            size_t g = (size_t)(k0 + row) * N + n0 + cc;
            uint32_t d = (uint32_t)(row * BST + cc) * 2;
            cpa16(base + offB(st) + d, B + g);
        }
        cpa_commit();
    };

    auto compute_tile = [&](int st) {
        const uint32_t sA = base + offA(st);
        const uint32_t sB = base + offB(st);
#pragma unroll
        for (int ksi = 0; ksi < 2; ksi++) {
            const int ks = ksi ^ phase;
            uint32_t ah[4][4], bh[8][2];
            // B first: trans-LDSM latency overlaps the A loads
#pragma unroll
            for (int nf2 = 0; nf2 < 4; nf2++) {
                int row = ks * 16 + (l & 7) + ((l >> 3) & 1) * 8;
                int col = wn + nf2 * 16 + (l >> 4) * 8;
                uint32_t off = (uint32_t)(row * BST + col) * 2;
                ldsmx4t(bh[nf2 * 2][0], bh[nf2 * 2][1], bh[nf2 * 2 + 1][0], bh[nf2 * 2 + 1][1], sB + off);
            }
#pragma unroll
            for (int mf = 0; mf < 4; mf++) {
                int row = wm + mf * 16 + (l & 7) + ((l >> 3) & 1) * 8;
                int col = ks * 16 + (l >> 4) * 8;
                uint32_t off = (uint32_t)(row * AST + col) * 2;
                ldsmx4(ah[mf][0], ah[mf][1], ah[mf][2], ah[mf][3], sA + off);
            }
#pragma unroll
            for (int mf = 0; mf < 4; mf++)
#pragma unroll
                for (int nf = 0; nf < 8; nf++)
                    mma_f16(acc[mf][nf], ah[mf], bh[nf]);
        }
    };

    const int NT = K / 32;
    load_tile(0, 0);
    load_tile(1, 32);
    for (int t = 0; t < NT; t++) {
        cpa_wait<NSTAGE - 2>();
        __syncthreads();
        if (t + NSTAGE - 1 < NT)
            load_tile((t + NSTAGE - 1) % NSTAGE, (t + NSTAGE - 1) * 32);
        else
            cpa_commit();            // keep group count invariant
        compute_tile(t % NSTAGE);
    }

    // ---- epilogue ----
#pragma unroll
    for (int mf = 0; mf < 4; mf++) {
        int r0 = m0 + wm + mf * 16 + (l >> 2);
#pragma unroll
        for (int nf = 0; nf < 8; nf++) {
            int col = n0 + wn + nf * 8 + (l & 3) * 2;
            float bx = bias[col], by = bias[col + 1];
            float2 o0 = make_float2(acc[mf][nf][0] + bx, acc[mf][nf][1] + by);
            float2 o1 = make_float2(acc[mf][nf][2] + bx, acc[mf][nf][3] + by);
            if (GELU) {
                o0.x = gelu_tanh(o0.x); o0.y = gelu_tanh(o0.y);
                o1.x = gelu_tanh(o1.x); o1.y = gelu_tanh(o1.y);
            }
            if (RES) {
                float2 ra = *(const float2*)(res + (size_t)r0 * N + col);
                float2 rb = *(const float2*)(res + (size_t)(r0 + 8) * N + col);
                o0.x += ra.x; o0.y += ra.y;
                o1.x += rb.x; o1.y += rb.y;
            }
            size_t i0 = (size_t)r0 * N + col;
            size_t i1 = (size_t)(r0 + 8) * N + col;
            if (WF32) {
                *(float2*)(Cf + i0) = o0;
                *(float2*)(Cf + i1) = o1;
            }
            if (WH) {
                *(__half2*)(Ch + i0) = __halves2half2(__float2half_rn(o0.x), __float2half_rn(o0.y));
                *(__half2*)(Ch + i1) = __halves2half2(__float2half_rn(o1.x), __float2half_rn(o1.y));
            }
        }
    }
}

// ---------------------------------------------------------------------------
// LayerNorm + sinusoidal PE -> fp32 + fp16 plane
// ---------------------------------------------------------------------------
__global__ void ln_pe_kernel(const float* __restrict__ x,
                             const float* __restrict__ gamma,
                             const float* __restrict__ beta,
                             float* __restrict__ outf,
                             f16* __restrict__ outh)
{
    const int row = blockIdx.x;
    const int tid = threadIdx.x;
    const float* xr = x + (size_t)row * DMODEL;

    float v0 = xr[tid], v1 = xr[tid + 256], v2 = xr[tid + 512];

    __shared__ float red[8];

    float s = v0 + v1 + v2;
#pragma unroll
    for (int o = 16; o > 0; o >>= 1) s += __shfl_xor_sync(0xffffffffu, s, o);
    if ((tid & 31) == 0) red[tid >> 5] = s;
    __syncthreads();
    float tot = red[0] + red[1] + red[2] + red[3] + red[4] + red[5] + red[6] + red[7];
    const float mean = tot / (float)DMODEL;
    __syncthreads();

    float d0 = v0 - mean, d1 = v1 - mean, d2 = v2 - mean;

    float sq = d0 * d0 + d1 * d1 + d2 * d2;
#pragma unroll
    for (int o = 16; o > 0; o >>= 1) sq += __shfl_xor_sync(0xffffffffu, sq, o);
    if ((tid & 31) == 0) red[tid >> 5] = sq;
    __syncthreads();
    float tot2 = red[0] + red[1] + red[2] + red[3] + red[4] + red[5] + red[6] + red[7];
    const float inv = rsqrtf(tot2 / (float)DMODEL + 1e-5f);

    const float n = (float)(row & (NTOK - 1));
    const float dv[3] = {d0, d1, d2};
    size_t rbase = (size_t)row * DMODEL;
#pragma unroll
    for (int j = 0; j < 3; j++) {
        int d = tid + j * 256;
        float freq = expf((float)(d & ~1) * (-9.210340371976184f / (float)DMODEL));
        float ang = n * freq;
        float pe = (d & 1) ? cosf(ang) : sinf(ang);
        float val = dv[j] * inv * gamma[d] + beta[d] + pe;
        outf[rbase + d] = val;
        outh[rbase + d] = __float2half_rn(val);
    }
}

// ---------------------------------------------------------------------------
// Windowed attention -> fp16 plane
// ---------------------------------------------------------------------------
__global__ void attn_kernel(const float* __restrict__ qkv,
                            f16* __restrict__ outh) {
    extern __shared__ float sm[];
    float* Qs = sm;
    float* Ks = sm + 64 * 65;
    float* Vs = sm + 2 * 64 * 65;
    float* Ss = sm + 3 * 64 * 65;

    const int blk = blockIdx.x;
    const int h = blk % NHEAD;
    const int w = (blk / NHEAD) % NWIN;
    const int b = blk / (NHEAD * NWIN);
    const int m0 = b * NTOK + w * WINSZ;
    const int tid = threadIdx.x;

    for (int idx = tid; idx < WINSZ * DHEAD; idx += 256) {
        int t = idx >> 6, d = idx & 63;
        size_t base = (size_t)(m0 + t) * QKVDIM + h * DHEAD + d;
        Qs[t * 65 + d] = qkv[base];
        Ks[t * 65 + d] = qkv[base + DMODEL];
        Vs[t * 65 + d] = qkv[base + 2 * DMODEL];
    }
    __syncthreads();

    for (int idx = tid; idx < WINSZ * WINSZ; idx += 256) {
        int q = idx >> 6, k = idx & 63;
        float s = 0.f;
#pragma unroll
        for (int i = 0; i < DHEAD; i++) s = fmaf(Qs[q * 65 + i], Ks[k * 65 + i], s);
        Ss[q * 65 + k] = s * 0.125f;
    }
    __syncthreads();

    if (tid < WINSZ) {
        float mx = -1e30f;
#pragma unroll 8
        for (int k = 0; k < WINSZ; k++) mx = fmaxf(mx, Ss[tid * 65 + k]);
        float sum = 0.f;
#pragma unroll 8
        for (int k = 0; k < WINSZ; k++) {
            float e = expf(Ss[tid * 65 + k] - mx);
            Ss[tid * 65 + k] = e;
            sum += e;
        }
        float invs = 1.f / sum;
#pragma unroll 8
        for (int k = 0; k < WINSZ; k++) Ss[tid * 65 + k] *= invs;
    }
    __syncthreads();

    for (int idx = tid; idx < WINSZ * DHEAD; idx += 256) {
        int q = idx >> 6, d = idx & 63;
        float o = 0.f;
#pragma unroll
        for (int k = 0; k < WINSZ; k++) o = fmaf(Ss[q * 65 + k], Vs[k * 65 + d], o);
        size_t oi = (size_t)(m0 + q) * DMODEL + h * DHEAD + d;
        outh[oi] = __float2half_rn(o);
    }
}

// ---------------------------------------------------------------------------
// Launch pipeline
// ---------------------------------------------------------------------------
extern "C" void kernel_launch(void* const* d_in, const int* in_sizes, int n_in,
                              void* d_out, int out_size)
{
    const float* input   = (const float*)d_in[0];
    const float* patch_w = (const float*)d_in[1];
    const float* patch_b = (const float*)d_in[2];
    const float* ln_g    = (const float*)d_in[3];
    const float* ln_b    = (const float*)d_in[4];
    const float* qkv_w   = (const float*)d_in[5];
    const float* qkv_b   = (const float*)d_in[6];
    const float* proj_w  = (const float*)d_in[7];
    const float* proj_b  = (const float*)d_in[8];
    const float* ff1_w   = (const float*)d_in[9];
    const float* ff1_b   = (const float*)d_in[10];
    const float* ff2_w   = (const float*)d_in[11];
    const float* ff2_b   = (const float*)d_in[12];
    float* out = (float*)d_out;

    f16 *A0, *wT, *qkvW, *projW, *ff1W, *ff2W;
    f16 *x0h, *hh, *yh, *attnh, *x2h;
    float *y, *x0, *qkvb, *x2;
    cudaGetSymbolAddress((void**)&A0, g_A0);
    cudaGetSymbolAddress((void**)&wT, g_wT);
    cudaGetSymbolAddress((void**)&qkvW, g_qkvW);
    cudaGetSymbolAddress((void**)&projW, g_projW);
    cudaGetSymbolAddress((void**)&ff1W, g_ff1W);
    cudaGetSymbolAddress((void**)&ff2W, g_ff2W);
    cudaGetSymbolAddress((void**)&x0h, g_x0h);
    cudaGetSymbolAddress((void**)&hh, g_hh);
    cudaGetSymbolAddress((void**)&yh, g_yh);
    cudaGetSymbolAddress((void**)&attnh, g_attnh);
    cudaGetSymbolAddress((void**)&x2h, g_x2h);
    cudaGetSymbolAddress((void**)&y, g_y);
    cudaGetSymbolAddress((void**)&x0, g_x0);
    cudaGetSymbolAddress((void**)&qkvb, g_qkv);
    cudaGetSymbolAddress((void**)&x2, g_x2);

    const int ATTN_SMEM = 4 * 64 * 65 * sizeof(float);
    cudaFuncSetAttribute(attn_kernel, cudaFuncAttributeMaxDynamicSharedMemorySize, ATTN_SMEM);
    cudaFuncSetAttribute(mma_gemm<false, false, true, false>, cudaFuncAttributeMaxDynamicSharedMemorySize, GEMM_SMEM);
    cudaFuncSetAttribute(mma_gemm<true, false, false, true>, cudaFuncAttributeMaxDynamicSharedMemorySize, GEMM_SMEM);
    cudaFuncSetAttribute(mma_gemm<false, false, false, true>, cudaFuncAttributeMaxDynamicSharedMemorySize, GEMM_SMEM);
    cudaFuncSetAttribute(mma_gemm<false, true, true, true>, cudaFuncAttributeMaxDynamicSharedMemorySize, GEMM_SMEM);
    cudaFuncSetAttribute(mma_gemm<false, true, true, false>, cudaFuncAttributeMaxDynamicSharedMemorySize, GEMM_SMEM);

    dim3 gD(DMODEL / 256, MTOT / 128);     // (3,128)
    dim3 gF(FDIM / 256, MTOT / 128);       // (12,128)
    dim3 gQ(QKVDIM / 256, MTOT / 128);     // (9,128)

    // 1. im2col
    {
        size_t total = (size_t)MTOT * DMODEL;
        im2col_kernel<<<(unsigned)((total + 255) / 256), 256>>>(input);
    }
    // 2. patch weight
    pack_wT_kernel<<<(DMODEL * DMODEL + 255) / 256, 256>>>(patch_w);
    // 3. ff1 weight
    convert_kernel<<<(DMODEL * FDIM + 255) / 256, 256>>>(ff1_w, ff1W, DMODEL * FDIM);
    // 4. patch embed -> fp32 y
    mma_gemm<false, false, true, false><<<gD, 256, GEMM_SMEM>>>(
        A0, wT, patch_b, nullptr, y, nullptr, MTOT, DMODEL, DMODEL);
    // 5. LN + PE -> x0 fp32 + plane
    ln_pe_kernel<<<MTOT, 256>>>(y, ln_g, ln_b, x0, x0h);
    // 6. ff1 + gelu -> h plane
    mma_gemm<true, false, false, true><<<gF, 256, GEMM_SMEM>>>(
        x0h, ff1W, ff1_b, nullptr, nullptr, hh, MTOT, FDIM, DMODEL);
    // 7. ff2 weight
    convert_kernel<<<(DMODEL * FDIM + 255) / 256, 256>>>(ff2_w, ff2W, DMODEL * FDIM);
    // 8. ff2 -> y plane
    mma_gemm<false, false, false, true><<<gD, 256, GEMM_SMEM>>>(
        hh, ff2W, ff2_b, nullptr, nullptr, yh, MTOT, DMODEL, FDIM);
    // 9. qkv weight
    convert_kernel<<<(DMODEL * QKVDIM + 255) / 256, 256>>>(qkv_w, qkvW, DMODEL * QKVDIM);
    // 10. qkv -> fp32
    mma_gemm<false, false, true, false><<<gQ, 256, GEMM_SMEM>>>(
        yh, qkvW, qkv_b, nullptr, qkvb, nullptr, MTOT, QKVDIM, DMODEL);
    // 11. attention -> plane
    attn_kernel<<<BATCH * NWIN * NHEAD, 256, ATTN_SMEM>>>(qkvb, attnh);
    // 12. proj weight
    convert_kernel<<<(DMODEL * DMODEL + 255) / 256, 256>>>(proj_w, projW, DMODEL * DMODEL);
    // 13. proj + residual(x0) -> x2 fp32 + plane
    mma_gemm<false, true, true, true><<<gD, 256, GEMM_SMEM>>>(
        attnh, projW, proj_b, x0, x2, x2h, MTOT, DMODEL, DMODEL);
    // 14. ff1 + gelu -> h plane
    mma_gemm<true, false, false, true><<<gF, 256, GEMM_SMEM>>>(
        x2h, ff1W, ff1_b, nullptr, nullptr, hh, MTOT, FDIM, DMODEL);
    // 15. ff2 + residual(x2) -> d_out
    mma_gemm<false, true, true, false><<<gD, 256, GEMM_SMEM>>>(
        hh, ff2W, ff2_b, x2, out, nullptr, MTOT, DMODEL, FDIM);
}

// round 16
// speedup vs baseline: 1.1296x; 1.1296x over previous
#include <cuda_runtime.h>
#include <cuda_fp16.h>
#include <math.h>
#include <stdint.h>

// ---------------------------------------------------------------------------
// Problem constants
// ---------------------------------------------------------------------------
#define BATCH 16
#define CH 3
#define IMG 512
#define PATCH 16
#define NTOK 1024
#define MTOT (BATCH * NTOK)    // 16384
#define DMODEL 768
#define FDIM 3072
#define QKVDIM 2304
#define NHEAD 12
#define DHEAD 64
#define WINSZ 64
#define NWIN 16

typedef __half f16;

// ---------------------------------------------------------------------------
// Static device scratch
// ---------------------------------------------------------------------------
__device__ f16 g_A0[(size_t)MTOT * DMODEL];    // im2col
__device__ f16 g_wT[(size_t)DMODEL * DMODEL];  // patch weight T [k][d]
__device__ f16 g_qkvW[(size_t)DMODEL * QKVDIM];
__device__ f16 g_projW[(size_t)DMODEL * DMODEL];
__device__ f16 g_ff1W[(size_t)DMODEL * FDIM];
__device__ f16 g_ff2W[(size_t)FDIM * DMODEL];

__device__ float g_pe[(size_t)NTOK * DMODEL];  // sinusoidal PE table (3 MB)

__device__ float g_y[(size_t)MTOT * DMODEL];
__device__ float g_x0[(size_t)MTOT * DMODEL];
__device__ f16   g_x0h[(size_t)MTOT * DMODEL];
__device__ f16   g_hh[(size_t)MTOT * FDIM];
__device__ f16   g_yh[(size_t)MTOT * DMODEL];
__device__ f16   g_qkvh[(size_t)MTOT * QKVDIM];
__device__ f16   g_attnh[(size_t)MTOT * DMODEL];
__device__ float g_x2[(size_t)MTOT * DMODEL];
__device__ f16   g_x2h[(size_t)MTOT * DMODEL];

// ---------------------------------------------------------------------------
// Helpers
// ---------------------------------------------------------------------------
__device__ __forceinline__ float gelu_tanh(float x) {
    float x3 = x * x * x;
    return 0.5f * x * (1.0f + tanhf(0.7978845608028654f * (x + 0.044715f * x3)));
}
__device__ __forceinline__ uint32_t smem_u32(const void* p) {
    return (uint32_t)__cvta_generic_to_shared(p);
}
__device__ __forceinline__ void cpa16(uint32_t dst, const void* src) {
    asm volatile("cp.async.cg.shared.global [%0], [%1], 16;" :: "r"(dst), "l"(src) : "memory");
}
__device__ __forceinline__ void cpa_commit() {
    asm volatile("cp.async.commit_group;" ::: "memory");
}
template <int N>
__device__ __forceinline__ void cpa_wait() {
    asm volatile("cp.async.wait_group %0;" :: "n"(N) : "memory");
}
__device__ __forceinline__ void ldsmx4(uint32_t& r0, uint32_t& r1, uint32_t& r2, uint32_t& r3, uint32_t a) {
    asm volatile("ldmatrix.sync.aligned.m8n8.x4.shared.b16 {%0,%1,%2,%3},[%4];"
                 : "=r"(r0), "=r"(r1), "=r"(r2), "=r"(r3) : "r"(a));
}
__device__ __forceinline__ void ldsmx4t(uint32_t& r0, uint32_t& r1, uint32_t& r2, uint32_t& r3, uint32_t a) {
    asm volatile("ldmatrix.sync.aligned.m8n8.x4.trans.shared.b16 {%0,%1,%2,%3},[%4];"
                 : "=r"(r0), "=r"(r1), "=r"(r2), "=r"(r3) : "r"(a));
}
__device__ __forceinline__ void mma_f16(float* d, const uint32_t* a, const uint32_t* b) {
    asm volatile("mma.sync.aligned.m16n8k16.row.col.f32.f16.f16.f32 "
                 "{%0,%1,%2,%3},{%4,%5,%6,%7},{%8,%9},{%0,%1,%2,%3};"
                 : "+f"(d[0]), "+f"(d[1]), "+f"(d[2]), "+f"(d[3])
                 : "r"(a[0]), "r"(a[1]), "r"(a[2]), "r"(a[3]), "r"(b[0]), "r"(b[1]));
}

// ---------------------------------------------------------------------------
// Producers
// ---------------------------------------------------------------------------
__global__ void im2col_kernel(const float* __restrict__ in) {
    size_t idx = (size_t)blockIdx.x * blockDim.x + threadIdx.x;
    size_t total = (size_t)MTOT * DMODEL;
    if (idx >= total) return;
    int k = (int)(idx % DMODEL);
    int m = (int)(idx / DMODEL);
    int q = k & 15;
    int p = (k >> 4) & 15;
    int c = k >> 8;
    int wp = m & 31;
    int hp = (m >> 5) & 31;
    int b = m >> 10;
    size_t src = (((size_t)(b * CH + c) * IMG) + (hp * PATCH + p)) * IMG + (wp * PATCH + q);
    g_A0[idx] = __float2half_rn(in[src]);
}

// patch_w [d][k] -> wT[k][d]
__global__ void pack_wT_kernel(const float* __restrict__ pw) {
    int idx = blockIdx.x * blockDim.x + threadIdx.x;
    if (idx >= DMODEL * DMODEL) return;
    int d = idx % DMODEL;
    int k = idx / DMODEL;
    g_wT[idx] = __float2half_rn(pw[(size_t)d * DMODEL + k]);
}

__global__ void convert_kernel(const float* __restrict__ src, f16* __restrict__ dst, int n) {
    int idx = blockIdx.x * blockDim.x + threadIdx.x;
    if (idx >= n) return;
    dst[idx] = __float2half_rn(src[idx]);
}

// PE table: pe[n][d], n in [0,1024)
__global__ void pe_table_kernel() {
    int idx = blockIdx.x * blockDim.x + threadIdx.x;
    if (idx >= NTOK * DMODEL) return;
    int d = idx % DMODEL;
    int n = idx / DMODEL;
    float freq = expf((float)(d & ~1) * (-9.210340371976184f / (float)DMODEL));
    float ang = (float)n * freq;
    g_pe[idx] = (d & 1) ? cosf(ang) : sinf(ang);
}

// ---------------------------------------------------------------------------
// Tensor-core GEMM: block 128x128, BK=64, 8 warps (warp 64x32), pure fp16,
// 1 MMA per product, 3-stage cp.async ring, 2 CTAs/SM, anti-phased warps.
// (R12 configuration — measured best at 1789us.)
// ---------------------------------------------------------------------------
#define AST 72    // As row stride (f16): 64 + 8 pad
#define BST 136   // Bs row stride: 128 + 8 pad
#define A_BYTES (128 * AST * 2)    // 18432
#define B_BYTES (64 * BST * 2)     // 17408
#define STAGE_BYTES (A_BYTES + B_BYTES)   // 35840
#define NSTAGE 3
#define GEMM_SMEM (NSTAGE * STAGE_BYTES)  // 107520

template <bool GELU, bool RES, bool WF32, bool WH>
__global__ __launch_bounds__(256, 2) void mma_gemm(
    const f16* __restrict__ A, const f16* __restrict__ B,
    const float* __restrict__ bias, const float* __restrict__ res,
    float* __restrict__ Cf, f16* __restrict__ Ch,
    int M, int N, int K)
{
    extern __shared__ char dsm[];
    const uint32_t base = smem_u32(dsm);
    auto offA = [&](int st) { return (uint32_t)(st * STAGE_BYTES); };
    auto offB = [&](int st) { return (uint32_t)(st * STAGE_BYTES + A_BYTES); };

    const int tid = threadIdx.x;
    const int l = tid & 31;
    const int w = tid >> 5;
    const int wm = (w & 1) * 64;
    const int wn = (w >> 1) * 32;
    const int phase = (w >> 2) & 1;   // anti-phase: half the warps start at ks=2
    const int m0 = blockIdx.y * 128;
    const int n0 = blockIdx.x * 128;

    float acc[4][4][4];
#pragma unroll
    for (int i = 0; i < 4; i++)
#pragma unroll
        for (int j = 0; j < 4; j++)
#pragma unroll
            for (int r = 0; r < 4; r++) acc[i][j][r] = 0.f;

    auto load_tile = [&](int st, int k0) {
        // A: 128x64 f16 = 1024 16B-lanes
#pragma unroll
        for (int s = 0; s < 4; s++) {
            int c = tid + s * 256;
            int row = c >> 3, cc = (c & 7) * 8;
            size_t g = (size_t)(m0 + row) * K + k0 + cc;
            uint32_t d = (uint32_t)(row * AST + cc) * 2;
            cpa16(base + offA(st) + d, A + g);
        }
        // B: 64x128 f16 = 1024 lanes
#pragma unroll
        for (int s = 0; s < 4; s++) {
            int c = tid + s * 256;
            int row = c >> 4, cc = (c & 15) * 8;
            size_t g = (size_t)(k0 + row) * N + n0 + cc;
            uint32_t d = (uint32_t)(row * BST + cc) * 2;
            cpa16(base + offB(st) + d, B + g);
        }
        cpa_commit();
    };

    auto compute_tile = [&](int st) {
        const uint32_t sA = base + offA(st);
        const uint32_t sB = base + offB(st);
#pragma unroll
        for (int ksi = 0; ksi < 4; ksi++) {
            const int ks = (ksi + phase * 2) & 3;
            uint32_t ah[4][4], bh[4][2];
            {
                int row = ks * 16 + (l & 7) + ((l >> 3) & 1) * 8;
                int col = wn + (l >> 4) * 8;
                uint32_t off = (uint32_t)(row * BST + col) * 2;
                ldsmx4t(bh[0][0], bh[0][1], bh[1][0], bh[1][1], sB + off);
                ldsmx4t(bh[2][0], bh[2][1], bh[3][0], bh[3][1], sB + off + 32);
            }
#pragma unroll
            for (int mf = 0; mf < 4; mf++) {
                int row = wm + mf * 16 + (l & 7) + ((l >> 3) & 1) * 8;
                int col = ks * 16 + (l >> 4) * 8;
                uint32_t off = (uint32_t)(row * AST + col) * 2;
                ldsmx4(ah[mf][0], ah[mf][1], ah[mf][2], ah[mf][3], sA + off);
            }
#pragma unroll
            for (int mf = 0; mf < 4; mf++)
#pragma unroll
                for (int nf = 0; nf < 4; nf++)
                    mma_f16(acc[mf][nf], ah[mf], bh[nf]);
        }
    };

    const int NT = K / 64;
    load_tile(0, 0);
    load_tile(1, 64);
    for (int t = 0; t < NT; t++) {
        cpa_wait<NSTAGE - 2>();
        __syncthreads();
        if (t + NSTAGE - 1 < NT)
            load_tile((t + NSTAGE - 1) % NSTAGE, (t + NSTAGE - 1) * 64);
        else
            cpa_commit();            // keep group count invariant
        compute_tile(t % NSTAGE);
    }

    // ---- epilogue ----
#pragma unroll
    for (int mf = 0; mf < 4; mf++) {
        int r0 = m0 + wm + mf * 16 + (l >> 2);
#pragma unroll
        for (int nf = 0; nf < 4; nf++) {
            int col = n0 + wn + nf * 8 + (l & 3) * 2;
            float bx = bias[col], by = bias[col + 1];
            float2 o0 = make_float2(acc[mf][nf][0] + bx, acc[mf][nf][1] + by);
            float2 o1 = make_float2(acc[mf][nf][2] + bx, acc[mf][nf][3] + by);
            if (GELU) {
                o0.x = gelu_tanh(o0.x); o0.y = gelu_tanh(o0.y);
                o1.x = gelu_tanh(o1.x); o1.y = gelu_tanh(o1.y);
            }
            if (RES) {
                float2 ra = *(const float2*)(res + (size_t)r0 * N + col);
                float2 rb = *(const float2*)(res + (size_t)(r0 + 8) * N + col);
                o0.x += ra.x; o0.y += ra.y;
                o1.x += rb.x; o1.y += rb.y;
            }
            size_t i0 = (size_t)r0 * N + col;
            size_t i1 = (size_t)(r0 + 8) * N + col;
            if (WF32) {
                *(float2*)(Cf + i0) = o0;
                *(float2*)(Cf + i1) = o1;
            }
            if (WH) {
                *(__half2*)(Ch + i0) = __halves2half2(__float2half_rn(o0.x), __float2half_rn(o0.y));
                *(__half2*)(Ch + i1) = __halves2half2(__float2half_rn(o1.x), __float2half_rn(o1.y));
            }
        }
    }
}

// ---------------------------------------------------------------------------
// LayerNorm + PE (table lookup) -> fp32 + fp16 plane
// ---------------------------------------------------------------------------
__global__ void ln_pe_kernel(const float* __restrict__ x,
                             const float* __restrict__ gamma,
                             const float* __restrict__ beta,
                             const float* __restrict__ pe,
                             float* __restrict__ outf,
                             f16* __restrict__ outh)
{
    const int row = blockIdx.x;
    const int tid = threadIdx.x;
    const float* xr = x + (size_t)row * DMODEL;

    float v0 = xr[tid], v1 = xr[tid + 256], v2 = xr[tid + 512];

    __shared__ float red[8];

    float s = v0 + v1 + v2;
#pragma unroll
    for (int o = 16; o > 0; o >>= 1) s += __shfl_xor_sync(0xffffffffu, s, o);
    if ((tid & 31) == 0) red[tid >> 5] = s;
    __syncthreads();
    float tot = red[0] + red[1] + red[2] + red[3] + red[4] + red[5] + red[6] + red[7];
    const float mean = tot / (float)DMODEL;
    __syncthreads();

    float d0 = v0 - mean, d1 = v1 - mean, d2 = v2 - mean;

    float sq = d0 * d0 + d1 * d1 + d2 * d2;
#pragma unroll
    for (int o = 16; o > 0; o >>= 1) sq += __shfl_xor_sync(0xffffffffu, sq, o);
    if ((tid & 31) == 0) red[tid >> 5] = sq;
    __syncthreads();
    float tot2 = red[0] + red[1] + red[2] + red[3] + red[4] + red[5] + red[6] + red[7];
    const float inv = rsqrtf(tot2 / (float)DMODEL + 1e-5f);

    const float* per = pe + (size_t)(row & (NTOK - 1)) * DMODEL;
    const float dv[3] = {d0, d1, d2};
    size_t rbase = (size_t)row * DMODEL;
#pragma unroll
    for (int j = 0; j < 3; j++) {
        int d = tid + j * 256;
        float val = dv[j] * inv * gamma[d] + beta[d] + per[d];
        outf[rbase + d] = val;
        outh[rbase + d] = __float2half_rn(val);
    }
}

// ---------------------------------------------------------------------------
// Windowed attention, fp16 qkv input -> fp16 plane output
// ---------------------------------------------------------------------------
__global__ void attn_kernel(const f16* __restrict__ qkv,
                            f16* __restrict__ outh) {
    extern __shared__ float sm[];
    float* Qs = sm;
    float* Ks = sm + 64 * 65;
    float* Vs = sm + 2 * 64 * 65;
    float* Ss = sm + 3 * 64 * 65;

    const int blk = blockIdx.x;
    const int h = blk % NHEAD;
    const int w = (blk / NHEAD) % NWIN;
    const int b = blk / (NHEAD * NWIN);
    const int m0 = b * NTOK + w * WINSZ;
    const int tid = threadIdx.x;

    for (int idx = tid; idx < WINSZ * DHEAD; idx += 256) {
        int t = idx >> 6, d = idx & 63;
        size_t base = (size_t)(m0 + t) * QKVDIM + h * DHEAD + d;
        Qs[t * 65 + d] = __half2float(qkv[base]);
        Ks[t * 65 + d] = __half2float(qkv[base + DMODEL]);
        Vs[t * 65 + d] = __half2float(qkv[base + 2 * DMODEL]);
    }
    __syncthreads();

    for (int idx = tid; idx < WINSZ * WINSZ; idx += 256) {
        int q = idx >> 6, k = idx & 63;
        float s = 0.f;
#pragma unroll
        for (int i = 0; i < DHEAD; i++) s = fmaf(Qs[q * 65 + i], Ks[k * 65 + i], s);
        Ss[q * 65 + k] = s * 0.125f;
    }
    __syncthreads();

    if (tid < WINSZ) {
        float mx = -1e30f;
#pragma unroll 8
        for (int k = 0; k < WINSZ; k++) mx = fmaxf(mx, Ss[tid * 65 + k]);
        float sum = 0.f;
#pragma unroll 8
        for (int k = 0; k < WINSZ; k++) {
            float e = expf(Ss[tid * 65 + k] - mx);
            Ss[tid * 65 + k] = e;
            sum += e;
        }
        float invs = 1.f / sum;
#pragma unroll 8
        for (int k = 0; k < WINSZ; k++) Ss[tid * 65 + k] *= invs;
    }
    __syncthreads();

    for (int idx = tid; idx < WINSZ * DHEAD; idx += 256) {
        int q = idx >> 6, d = idx & 63;
        float o = 0.f;
#pragma unroll
        for (int k = 0; k < WINSZ; k++) o = fmaf(Ss[q * 65 + k], Vs[k * 65 + d], o);
        size_t oi = (size_t)(m0 + q) * DMODEL + h * DHEAD + d;
        outh[oi] = __float2half_rn(o);
    }
}

// ---------------------------------------------------------------------------
// Launch pipeline
// ---------------------------------------------------------------------------
extern "C" void kernel_launch(void* const* d_in, const int* in_sizes, int n_in,
                              void* d_out, int out_size)
{
    const float* input   = (const float*)d_in[0];
    const float* patch_w = (const float*)d_in[1];
    const float* patch_b = (const float*)d_in[2];
    const float* ln_g    = (const float*)d_in[3];
    const float* ln_b    = (const float*)d_in[4];
    const float* qkv_w   = (const float*)d_in[5];
    const float* qkv_b   = (const float*)d_in[6];
    const float* proj_w  = (const float*)d_in[7];
    const float* proj_b  = (const float*)d_in[8];
    const float* ff1_w   = (const float*)d_in[9];
    const float* ff1_b   = (const float*)d_in[10];
    const float* ff2_w   = (const float*)d_in[11];
    const float* ff2_b   = (const float*)d_in[12];
    float* out = (float*)d_out;

    f16 *A0, *wT, *qkvW, *projW, *ff1W, *ff2W;
    f16 *x0h, *hh, *yh, *qkvh, *attnh, *x2h;
    float *y, *x0, *x2, *pe;
    cudaGetSymbolAddress((void**)&A0, g_A0);
    cudaGetSymbolAddress((void**)&wT, g_wT);
    cudaGetSymbolAddress((void**)&qkvW, g_qkvW);
    cudaGetSymbolAddress((void**)&projW, g_projW);
    cudaGetSymbolAddress((void**)&ff1W, g_ff1W);
    cudaGetSymbolAddress((void**)&ff2W, g_ff2W);
    cudaGetSymbolAddress((void**)&x0h, g_x0h);
    cudaGetSymbolAddress((void**)&hh, g_hh);
    cudaGetSymbolAddress((void**)&yh, g_yh);
    cudaGetSymbolAddress((void**)&qkvh, g_qkvh);
    cudaGetSymbolAddress((void**)&attnh, g_attnh);
    cudaGetSymbolAddress((void**)&x2h, g_x2h);
    cudaGetSymbolAddress((void**)&y, g_y);
    cudaGetSymbolAddress((void**)&x0, g_x0);
    cudaGetSymbolAddress((void**)&x2, g_x2);
    cudaGetSymbolAddress((void**)&pe, g_pe);

    const int ATTN_SMEM = 4 * 64 * 65 * sizeof(float);
    cudaFuncSetAttribute(attn_kernel, cudaFuncAttributeMaxDynamicSharedMemorySize, ATTN_SMEM);
    cudaFuncSetAttribute(mma_gemm<false, false, true, false>, cudaFuncAttributeMaxDynamicSharedMemorySize, GEMM_SMEM);
    cudaFuncSetAttribute(mma_gemm<true, false, false, true>, cudaFuncAttributeMaxDynamicSharedMemorySize, GEMM_SMEM);
    cudaFuncSetAttribute(mma_gemm<false, false, false, true>, cudaFuncAttributeMaxDynamicSharedMemorySize, GEMM_SMEM);
    cudaFuncSetAttribute(mma_gemm<false, true, true, true>, cudaFuncAttributeMaxDynamicSharedMemorySize, GEMM_SMEM);
    cudaFuncSetAttribute(mma_gemm<false, true, true, false>, cudaFuncAttributeMaxDynamicSharedMemorySize, GEMM_SMEM);

    dim3 gD(DMODEL / 128, MTOT / 128);     // (6,128)
    dim3 gF(FDIM / 128, MTOT / 128);       // (24,128)
    dim3 gQ(QKVDIM / 128, MTOT / 128);     // (18,128)

    // 1. im2col
    {
        size_t total = (size_t)MTOT * DMODEL;
        im2col_kernel<<<(unsigned)((total + 255) / 256), 256>>>(input);
    }
    // 2. patch weight
    pack_wT_kernel<<<(DMODEL * DMODEL + 255) / 256, 256>>>(patch_w);
    // 3. PE table
    pe_table_kernel<<<(NTOK * DMODEL + 255) / 256, 256>>>();
    // 4. ff1 weight
    convert_kernel<<<(DMODEL * FDIM + 255) / 256, 256>>>(ff1_w, ff1W, DMODEL * FDIM);
    // 5. patch embed -> fp32 y
    mma_gemm<false, false, true, false><<<gD, 256, GEMM_SMEM>>>(
        A0, wT, patch_b, nullptr, y, nullptr, MTOT, DMODEL, DMODEL);
    // 6. LN + PE -> x0 fp32 + plane
    ln_pe_kernel<<<MTOT, 256>>>(y, ln_g, ln_b, pe, x0, x0h);
    // 7. ff1 + gelu -> h plane
    mma_gemm<true, false, false, true><<<gF, 256, GEMM_SMEM>>>(
        x0h, ff1W, ff1_b, nullptr, nullptr, hh, MTOT, FDIM, DMODEL);
    // 8. ff2 weight
    convert_kernel<<<(DMODEL * FDIM + 255) / 256, 256>>>(ff2_w, ff2W, DMODEL * FDIM);
    // 9. ff2 -> y plane
    mma_gemm<false, false, false, true><<<gD, 256, GEMM_SMEM>>>(
        hh, ff2W, ff2_b, nullptr, nullptr, yh, MTOT, DMODEL, FDIM);
    // 10. qkv weight
    convert_kernel<<<(DMODEL * QKVDIM + 255) / 256, 256>>>(qkv_w, qkvW, DMODEL * QKVDIM);
    // 11. qkv -> fp16 plane
    mma_gemm<false, false, false, true><<<gQ, 256, GEMM_SMEM>>>(
        yh, qkvW, qkv_b, nullptr, nullptr, qkvh, MTOT, QKVDIM, DMODEL);
    // 12. attention -> plane
    attn_kernel<<<BATCH * NWIN * NHEAD, 256, ATTN_SMEM>>>(qkvh, attnh);
    // 13. proj weight
    convert_kernel<<<(DMODEL * DMODEL + 255) / 256, 256>>>(proj_w, projW, DMODEL * DMODEL);
    // 14. proj + residual(x0) -> x2 fp32 + plane
    mma_gemm<false, true, true, true><<<gD, 256, GEMM_SMEM>>>(
        attnh, projW, proj_b, x0, x2, x2h, MTOT, DMODEL, DMODEL);
    // 15. ff1 + gelu -> h plane
    mma_gemm<true, false, false, true><<<gF, 256, GEMM_SMEM>>>(
        x2h, ff1W, ff1_b, nullptr, nullptr, hh, MTOT, FDIM, DMODEL);
    // 16. ff2 + residual(x2) -> d_out
    mma_gemm<false, true, true, false><<<gD, 256, GEMM_SMEM>>>(
        hh, ff2W, ff2_b, x2, out, nullptr, MTOT, DMODEL, FDIM);
}

// round 17
// speedup vs baseline: 1.1338x; 1.0037x over previous
#include <cuda_runtime.h>
#include <cuda_fp16.h>
#include <math.h>
#include <stdint.h>

// ---------------------------------------------------------------------------
// Problem constants
// ---------------------------------------------------------------------------
#define BATCH 16
#define CH 3
#define IMG 512
#define PATCH 16
#define NTOK 1024
#define MTOT (BATCH * NTOK)    // 16384
#define DMODEL 768
#define FDIM 3072
#define QKVDIM 2304
#define NHEAD 12
#define DHEAD 64
#define WINSZ 64
#define NWIN 16

typedef __half f16;

// ---------------------------------------------------------------------------
// Static device scratch
// ---------------------------------------------------------------------------
__device__ f16 g_A0[(size_t)MTOT * DMODEL];    // im2col
__device__ f16 g_wT[(size_t)DMODEL * DMODEL];  // patch weight T [k][d]
__device__ f16 g_qkvW[(size_t)DMODEL * QKVDIM];
__device__ f16 g_projW[(size_t)DMODEL * DMODEL];
__device__ f16 g_ff1W[(size_t)DMODEL * FDIM];
__device__ f16 g_ff2W[(size_t)FDIM * DMODEL];

__device__ float g_pe[(size_t)NTOK * DMODEL];  // sinusoidal PE table (3 MB)

__device__ f16   g_yh0[(size_t)MTOT * DMODEL]; // patch out (fp16)
__device__ float g_x0[(size_t)MTOT * DMODEL];
__device__ f16   g_x0h[(size_t)MTOT * DMODEL];
__device__ f16   g_hh[(size_t)MTOT * FDIM];
__device__ f16   g_yh[(size_t)MTOT * DMODEL];
__device__ f16   g_qkvh[(size_t)MTOT * QKVDIM];
__device__ f16   g_attnh[(size_t)MTOT * DMODEL];
__device__ float g_x2[(size_t)MTOT * DMODEL];
__device__ f16   g_x2h[(size_t)MTOT * DMODEL];

// ---------------------------------------------------------------------------
// Helpers
// ---------------------------------------------------------------------------
__device__ __forceinline__ float gelu_tanh(float x) {
    float x3 = x * x * x;
    return 0.5f * x * (1.0f + tanhf(0.7978845608028654f * (x + 0.044715f * x3)));
}
__device__ __forceinline__ uint32_t smem_u32(const void* p) {
    return (uint32_t)__cvta_generic_to_shared(p);
}
__device__ __forceinline__ void cpa16(uint32_t dst, const void* src) {
    asm volatile("cp.async.cg.shared.global [%0], [%1], 16;" :: "r"(dst), "l"(src) : "memory");
}
__device__ __forceinline__ void cpa_commit() {
    asm volatile("cp.async.commit_group;" ::: "memory");
}
template <int N>
__device__ __forceinline__ void cpa_wait() {
    asm volatile("cp.async.wait_group %0;" :: "n"(N) : "memory");
}
__device__ __forceinline__ void ldsmx4(uint32_t& r0, uint32_t& r1, uint32_t& r2, uint32_t& r3, uint32_t a) {
    asm volatile("ldmatrix.sync.aligned.m8n8.x4.shared.b16 {%0,%1,%2,%3},[%4];"
                 : "=r"(r0), "=r"(r1), "=r"(r2), "=r"(r3) : "r"(a));
}
__device__ __forceinline__ void ldsmx4t(uint32_t& r0, uint32_t& r1, uint32_t& r2, uint32_t& r3, uint32_t a) {
    asm volatile("ldmatrix.sync.aligned.m8n8.x4.trans.shared.b16 {%0,%1,%2,%3},[%4];"
                 : "=r"(r0), "=r"(r1), "=r"(r2), "=r"(r3) : "r"(a));
}
__device__ __forceinline__ void mma_f16(float* d, const uint32_t* a, const uint32_t* b) {
    asm volatile("mma.sync.aligned.m16n8k16.row.col.f32.f16.f16.f32 "
                 "{%0,%1,%2,%3},{%4,%5,%6,%7},{%8,%9},{%0,%1,%2,%3};"
                 : "+f"(d[0]), "+f"(d[1]), "+f"(d[2]), "+f"(d[3])
                 : "r"(a[0]), "r"(a[1]), "r"(a[2]), "r"(a[3]), "r"(b[0]), "r"(b[1]));
}

// ---------------------------------------------------------------------------
// Producers
// ---------------------------------------------------------------------------
__global__ void im2col_kernel(const float* __restrict__ in) {
    size_t idx = (size_t)blockIdx.x * blockDim.x + threadIdx.x;
    size_t total = (size_t)MTOT * DMODEL;
    if (idx >= total) return;
    int k = (int)(idx % DMODEL);
    int m = (int)(idx / DMODEL);
    int q = k & 15;
    int p = (k >> 4) & 15;
    int c = k >> 8;
    int wp = m & 31;
    int hp = (m >> 5) & 31;
    int b = m >> 10;
    size_t src = (((size_t)(b * CH + c) * IMG) + (hp * PATCH + p)) * IMG + (wp * PATCH + q);
    g_A0[idx] = __float2half_rn(in[src]);
}

// patch_w [d][k] -> wT[k][d]
__global__ void pack_wT_kernel(const float* __restrict__ pw) {
    int idx = blockIdx.x * blockDim.x + threadIdx.x;
    if (idx >= DMODEL * DMODEL) return;
    int d = idx % DMODEL;
    int k = idx / DMODEL;
    g_wT[idx] = __float2half_rn(pw[(size_t)d * DMODEL + k]);
}

// one kernel converting all four big weights (ff1, ff2, qkv, proj)
#define N_FF  (DMODEL * FDIM)     // 2359296
#define N_QKV (DMODEL * QKVDIM)   // 1769472
#define N_PR  (DMODEL * DMODEL)   // 589824
#define N_ALL (2 * N_FF + N_QKV + N_PR)
__global__ void convert_all_kernel(const float* __restrict__ ff1_w,
                                   const float* __restrict__ ff2_w,
                                   const float* __restrict__ qkv_w,
                                   const float* __restrict__ proj_w) {
    int idx = blockIdx.x * blockDim.x + threadIdx.x;
    if (idx >= N_ALL) return;
    if (idx < N_FF) {
        g_ff1W[idx] = __float2half_rn(ff1_w[idx]);
    } else if (idx < 2 * N_FF) {
        int i = idx - N_FF;
        g_ff2W[i] = __float2half_rn(ff2_w[i]);
    } else if (idx < 2 * N_FF + N_QKV) {
        int i = idx - 2 * N_FF;
        g_qkvW[i] = __float2half_rn(qkv_w[i]);
    } else {
        int i = idx - 2 * N_FF - N_QKV;
        g_projW[i] = __float2half_rn(proj_w[i]);
    }
}

// PE table: pe[n][d], n in [0,1024)
__global__ void pe_table_kernel() {
    int idx = blockIdx.x * blockDim.x + threadIdx.x;
    if (idx >= NTOK * DMODEL) return;
    int d = idx % DMODEL;
    int n = idx / DMODEL;
    float freq = expf((float)(d & ~1) * (-9.210340371976184f / (float)DMODEL));
    float ang = (float)n * freq;
    g_pe[idx] = (d & 1) ? cosf(ang) : sinf(ang);
}

// ---------------------------------------------------------------------------
// Tensor-core GEMM: block 128x128, BK=64, 8 warps (warp 64x32), pure fp16,
// 1 MMA per product, 3-stage cp.async ring, 2 CTAs/SM, anti-phased warps.
// ---------------------------------------------------------------------------
#define AST 72    // As row stride (f16): 64 + 8 pad
#define BST 136   // Bs row stride: 128 + 8 pad
#define A_BYTES (128 * AST * 2)    // 18432
#define B_BYTES (64 * BST * 2)     // 17408
#define STAGE_BYTES (A_BYTES + B_BYTES)   // 35840
#define NSTAGE 3
#define GEMM_SMEM (NSTAGE * STAGE_BYTES)  // 107520

template <bool GELU, bool RES, bool WF32, bool WH>
__global__ __launch_bounds__(256, 2) void mma_gemm(
    const f16* __restrict__ A, const f16* __restrict__ B,
    const float* __restrict__ bias, const float* __restrict__ res,
    float* __restrict__ Cf, f16* __restrict__ Ch,
    int M, int N, int K)
{
    extern __shared__ char dsm[];
    const uint32_t base = smem_u32(dsm);
    auto offA = [&](int st) { return (uint32_t)(st * STAGE_BYTES); };
    auto offB = [&](int st) { return (uint32_t)(st * STAGE_BYTES + A_BYTES); };

    const int tid = threadIdx.x;
    const int l = tid & 31;
    const int w = tid >> 5;
    const int wm = (w & 1) * 64;
    const int wn = (w >> 1) * 32;
    const int phase = (w >> 2) & 1;
    const int m0 = blockIdx.y * 128;
    const int n0 = blockIdx.x * 128;

    float acc[4][4][4];
#pragma unroll
    for (int i = 0; i < 4; i++)
#pragma unroll
        for (int j = 0; j < 4; j++)
#pragma unroll
            for (int r = 0; r < 4; r++) acc[i][j][r] = 0.f;

    auto load_tile = [&](int st, int k0) {
#pragma unroll
        for (int s = 0; s < 4; s++) {
            int c = tid + s * 256;
            int row = c >> 3, cc = (c & 7) * 8;
            size_t g = (size_t)(m0 + row) * K + k0 + cc;
            uint32_t d = (uint32_t)(row * AST + cc) * 2;
            cpa16(base + offA(st) + d, A + g);
        }
#pragma unroll
        for (int s = 0; s < 4; s++) {
            int c = tid + s * 256;
            int row = c >> 4, cc = (c & 15) * 8;
            size_t g = (size_t)(k0 + row) * N + n0 + cc;
            uint32_t d = (uint32_t)(row * BST + cc) * 2;
            cpa16(base + offB(st) + d, B + g);
        }
        cpa_commit();
    };

    auto compute_tile = [&](int st) {
        const uint32_t sA = base + offA(st);
        const uint32_t sB = base + offB(st);
#pragma unroll
        for (int ksi = 0; ksi < 4; ksi++) {
            const int ks = (ksi + phase * 2) & 3;
            uint32_t ah[4][4], bh[4][2];
            {
                int row = ks * 16 + (l & 7) + ((l >> 3) & 1) * 8;
                int col = wn + (l >> 4) * 8;
                uint32_t off = (uint32_t)(row * BST + col) * 2;
                ldsmx4t(bh[0][0], bh[0][1], bh[1][0], bh[1][1], sB + off);
                ldsmx4t(bh[2][0], bh[2][1], bh[3][0], bh[3][1], sB + off + 32);
            }
#pragma unroll
            for (int mf = 0; mf < 4; mf++) {
                int row = wm + mf * 16 + (l & 7) + ((l >> 3) & 1) * 8;
                int col = ks * 16 + (l >> 4) * 8;
                uint32_t off = (uint32_t)(row * AST + col) * 2;
                ldsmx4(ah[mf][0], ah[mf][1], ah[mf][2], ah[mf][3], sA + off);
            }
#pragma unroll
            for (int mf = 0; mf < 4; mf++)
#pragma unroll
                for (int nf = 0; nf < 4; nf++)
                    mma_f16(acc[mf][nf], ah[mf], bh[nf]);
        }
    };

    const int NT = K / 64;
    load_tile(0, 0);
    load_tile(1, 64);
    for (int t = 0; t < NT; t++) {
        cpa_wait<NSTAGE - 2>();
        __syncthreads();
        if (t + NSTAGE - 1 < NT)
            load_tile((t + NSTAGE - 1) % NSTAGE, (t + NSTAGE - 1) * 64);
        else
            cpa_commit();
        compute_tile(t % NSTAGE);
    }

    // ---- epilogue ----
#pragma unroll
    for (int mf = 0; mf < 4; mf++) {
        int r0 = m0 + wm + mf * 16 + (l >> 2);
#pragma unroll
        for (int nf = 0; nf < 4; nf++) {
            int col = n0 + wn + nf * 8 + (l & 3) * 2;
            float bx = bias[col], by = bias[col + 1];
            float2 o0 = make_float2(acc[mf][nf][0] + bx, acc[mf][nf][1] + by);
            float2 o1 = make_float2(acc[mf][nf][2] + bx, acc[mf][nf][3] + by);
            if (GELU) {
                o0.x = gelu_tanh(o0.x); o0.y = gelu_tanh(o0.y);
                o1.x = gelu_tanh(o1.x); o1.y = gelu_tanh(o1.y);
            }
            if (RES) {
                float2 ra = *(const float2*)(res + (size_t)r0 * N + col);
                float2 rb = *(const float2*)(res + (size_t)(r0 + 8) * N + col);
                o0.x += ra.x; o0.y += ra.y;
                o1.x += rb.x; o1.y += rb.y;
            }
            size_t i0 = (size_t)r0 * N + col;
            size_t i1 = (size_t)(r0 + 8) * N + col;
            if (WF32) {
                *(float2*)(Cf + i0) = o0;
                *(float2*)(Cf + i1) = o1;
            }
            if (WH) {
                *(__half2*)(Ch + i0) = __halves2half2(__float2half_rn(o0.x), __float2half_rn(o0.y));
                *(__half2*)(Ch + i1) = __halves2half2(__float2half_rn(o1.x), __float2half_rn(o1.y));
            }
        }
    }
}

// ---------------------------------------------------------------------------
// LayerNorm (fp16 input) + PE table -> fp32 + fp16 plane
// ---------------------------------------------------------------------------
__global__ void ln_pe_kernel(const f16* __restrict__ x,
                             const float* __restrict__ gamma,
                             const float* __restrict__ beta,
                             const float* __restrict__ pe,
                             float* __restrict__ outf,
                             f16* __restrict__ outh)
{
    const int row = blockIdx.x;
    const int tid = threadIdx.x;
    const f16* xr = x + (size_t)row * DMODEL;

    float v0 = __half2float(xr[tid]);
    float v1 = __half2float(xr[tid + 256]);
    float v2 = __half2float(xr[tid + 512]);

    __shared__ float red[8];

    float s = v0 + v1 + v2;
#pragma unroll
    for (int o = 16; o > 0; o >>= 1) s += __shfl_xor_sync(0xffffffffu, s, o);
    if ((tid & 31) == 0) red[tid >> 5] = s;
    __syncthreads();
    float tot = red[0] + red[1] + red[2] + red[3] + red[4] + red[5] + red[6] + red[7];
    const float mean = tot / (float)DMODEL;
    __syncthreads();

    float d0 = v0 - mean, d1 = v1 - mean, d2 = v2 - mean;

    float sq = d0 * d0 + d1 * d1 + d2 * d2;
#pragma unroll
    for (int o = 16; o > 0; o >>= 1) sq += __shfl_xor_sync(0xffffffffu, sq, o);
    if ((tid & 31) == 0) red[tid >> 5] = sq;
    __syncthreads();
    float tot2 = red[0] + red[1] + red[2] + red[3] + red[4] + red[5] + red[6] + red[7];
    const float inv = rsqrtf(tot2 / (float)DMODEL + 1e-5f);

    const float* per = pe + (size_t)(row & (NTOK - 1)) * DMODEL;
    const float dv[3] = {d0, d1, d2};
    size_t rbase = (size_t)row * DMODEL;
#pragma unroll
    for (int j = 0; j < 3; j++) {
        int d = tid + j * 256;
        float val = dv[j] * inv * gamma[d] + beta[d] + per[d];
        outf[rbase + d] = val;
        outh[rbase + d] = __float2half_rn(val);
    }
}

// ---------------------------------------------------------------------------
// Windowed attention, fp16 qkv input -> fp16 plane output
// ---------------------------------------------------------------------------
__global__ void attn_kernel(const f16* __restrict__ qkv,
                            f16* __restrict__ outh) {
    extern __shared__ float sm[];
    float* Qs = sm;
    float* Ks = sm + 64 * 65;
    float* Vs = sm + 2 * 64 * 65;
    float* Ss = sm + 3 * 64 * 65;

    const int blk = blockIdx.x;
    const int h = blk % NHEAD;
    const int w = (blk / NHEAD) % NWIN;
    const int b = blk / (NHEAD * NWIN);
    const int m0 = b * NTOK + w * WINSZ;
    const int tid = threadIdx.x;

    for (int idx = tid; idx < WINSZ * DHEAD; idx += 256) {
        int t = idx >> 6, d = idx & 63;
        size_t base = (size_t)(m0 + t) * QKVDIM + h * DHEAD + d;
        Qs[t * 65 + d] = __half2float(qkv[base]);
        Ks[t * 65 + d] = __half2float(qkv[base + DMODEL]);
        Vs[t * 65 + d] = __half2float(qkv[base + 2 * DMODEL]);
    }
    __syncthreads();

    for (int idx = tid; idx < WINSZ * WINSZ; idx += 256) {
        int q = idx >> 6, k = idx & 63;
        float s = 0.f;
#pragma unroll
        for (int i = 0; i < DHEAD; i++) s = fmaf(Qs[q * 65 + i], Ks[k * 65 + i], s);
        Ss[q * 65 + k] = s * 0.125f;
    }
    __syncthreads();

    if (tid < WINSZ) {
        float mx = -1e30f;
#pragma unroll 8
        for (int k = 0; k < WINSZ; k++) mx = fmaxf(mx, Ss[tid * 65 + k]);
        float sum = 0.f;
#pragma unroll 8
        for (int k = 0; k < WINSZ; k++) {
            float e = expf(Ss[tid * 65 + k] - mx);
            Ss[tid * 65 + k] = e;
            sum += e;
        }
        float invs = 1.f / sum;
#pragma unroll 8
        for (int k = 0; k < WINSZ; k++) Ss[tid * 65 + k] *= invs;
    }
    __syncthreads();

    for (int idx = tid; idx < WINSZ * DHEAD; idx += 256) {
        int q = idx >> 6, d = idx & 63;
        float o = 0.f;
#pragma unroll
        for (int k = 0; k < WINSZ; k++) o = fmaf(Ss[q * 65 + k], Vs[k * 65 + d], o);
        size_t oi = (size_t)(m0 + q) * DMODEL + h * DHEAD + d;
        outh[oi] = __float2half_rn(o);
    }
}

// ---------------------------------------------------------------------------
// Launch pipeline
// ---------------------------------------------------------------------------
extern "C" void kernel_launch(void* const* d_in, const int* in_sizes, int n_in,
                              void* d_out, int out_size)
{
    const float* input   = (const float*)d_in[0];
    const float* patch_w = (const float*)d_in[1];
    const float* patch_b = (const float*)d_in[2];
    const float* ln_g    = (const float*)d_in[3];
    const float* ln_b    = (const float*)d_in[4];
    const float* qkv_w   = (const float*)d_in[5];
    const float* qkv_b   = (const float*)d_in[6];
    const float* proj_w  = (const float*)d_in[7];
    const float* proj_b  = (const float*)d_in[8];
    const float* ff1_w   = (const float*)d_in[9];
    const float* ff1_b   = (const float*)d_in[10];
    const float* ff2_w   = (const float*)d_in[11];
    const float* ff2_b   = (const float*)d_in[12];
    float* out = (float*)d_out;

    f16 *A0, *wT, *qkvW, *projW, *ff1W, *ff2W;
    f16 *yh0, *x0h, *hh, *yh, *qkvh, *attnh, *x2h;
    float *x0, *x2, *pe;
    cudaGetSymbolAddress((void**)&A0, g_A0);
    cudaGetSymbolAddress((void**)&wT, g_wT);
    cudaGetSymbolAddress((void**)&qkvW, g_qkvW);
    cudaGetSymbolAddress((void**)&projW, g_projW);
    cudaGetSymbolAddress((void**)&ff1W, g_ff1W);
    cudaGetSymbolAddress((void**)&ff2W, g_ff2W);
    cudaGetSymbolAddress((void**)&yh0, g_yh0);
    cudaGetSymbolAddress((void**)&x0h, g_x0h);
    cudaGetSymbolAddress((void**)&hh, g_hh);
    cudaGetSymbolAddress((void**)&yh, g_yh);
    cudaGetSymbolAddress((void**)&qkvh, g_qkvh);
    cudaGetSymbolAddress((void**)&attnh, g_attnh);
    cudaGetSymbolAddress((void**)&x2h, g_x2h);
    cudaGetSymbolAddress((void**)&x0, g_x0);
    cudaGetSymbolAddress((void**)&x2, g_x2);
    cudaGetSymbolAddress((void**)&pe, g_pe);

    const int ATTN_SMEM = 4 * 64 * 65 * sizeof(float);
    cudaFuncSetAttribute(attn_kernel, cudaFuncAttributeMaxDynamicSharedMemorySize, ATTN_SMEM);
    cudaFuncSetAttribute(mma_gemm<false, false, false, true>, cudaFuncAttributeMaxDynamicSharedMemorySize, GEMM_SMEM);
    cudaFuncSetAttribute(mma_gemm<true, false, false, true>, cudaFuncAttributeMaxDynamicSharedMemorySize, GEMM_SMEM);
    cudaFuncSetAttribute(mma_gemm<false, true, true, true>, cudaFuncAttributeMaxDynamicSharedMemorySize, GEMM_SMEM);
    cudaFuncSetAttribute(mma_gemm<false, true, true, false>, cudaFuncAttributeMaxDynamicSharedMemorySize, GEMM_SMEM);

    dim3 gD(DMODEL / 128, MTOT / 128);     // (6,128)
    dim3 gF(FDIM / 128, MTOT / 128);       // (24,128)
    dim3 gQ(QKVDIM / 128, MTOT / 128);     // (18,128)

    // 1. im2col
    {
        size_t total = (size_t)MTOT * DMODEL;
        im2col_kernel<<<(unsigned)((total + 255) / 256), 256>>>(input);
    }
    // 2. patch weight
    pack_wT_kernel<<<(DMODEL * DMODEL + 255) / 256, 256>>>(patch_w);
    // 3. PE table
    pe_table_kernel<<<(NTOK * DMODEL + 255) / 256, 256>>>();
    // 4. all weight converts (single kernel)
    convert_all_kernel<<<(N_ALL + 255) / 256, 256>>>(ff1_w, ff2_w, qkv_w, proj_w);
    // 5. patch embed -> fp16 yh0
    mma_gemm<false, false, false, true><<<gD, 256, GEMM_SMEM>>>(
        A0, wT, patch_b, nullptr, nullptr, yh0, MTOT, DMODEL, DMODEL);
    // 6. LN + PE -> x0 fp32 + plane
    ln_pe_kernel<<<MTOT, 256>>>(yh0, ln_g, ln_b, pe, x0, x0h);
    // 7. ff1 + gelu -> h plane
    mma_gemm<true, false, false, true><<<gF, 256, GEMM_SMEM>>>(
        x0h, ff1W, ff1_b, nullptr, nullptr, hh, MTOT, FDIM, DMODEL);
    // 8. ff2 -> y plane
    mma_gemm<false, false, false, true><<<gD, 256, GEMM_SMEM>>>(
        hh, ff2W, ff2_b, nullptr, nullptr, yh, MTOT, DMODEL, FDIM);
    // 9. qkv -> fp16 plane
    mma_gemm<false, false, false, true><<<gQ, 256, GEMM_SMEM>>>(
        yh, qkvW, qkv_b, nullptr, nullptr, qkvh, MTOT, QKVDIM, DMODEL);
    // 10. attention -> plane
    attn_kernel<<<BATCH * NWIN * NHEAD, 256, ATTN_SMEM>>>(qkvh, attnh);
    // 11. proj + residual(x0) -> x2 fp32 + plane
    mma_gemm<false, true, true, true><<<gD, 256, GEMM_SMEM>>>(
        attnh, projW, proj_b, x0, x2, x2h, MTOT, DMODEL, DMODEL);
    // 12. ff1 + gelu -> h plane
    mma_gemm<true, false, false, true><<<gF, 256, GEMM_SMEM>>>(
        x2h, ff1W, ff1_b, nullptr, nullptr, hh, MTOT, FDIM, DMODEL);
    // 13. ff2 + residual(x2) -> d_out
    mma_gemm<false, true, true, false><<<gD, 256, GEMM_SMEM>>>(
        hh, ff2W, ff2_b, x2, out, nullptr, MTOT, DMODEL, FDIM);
}